// round 13
// baseline (speedup 1.0000x reference)
#include <cuda_runtime.h>
#include <cuda_fp16.h>
#include <cstdint>

// ---------------- problem constants ----------------
constexpr int Bn  = 8;
constexpr int Cn  = 192;
constexpr int Hn  = 224;
constexpr int Wn  = 224;
constexpr int WSz = 7;
constexpr int HW  = Hn * Wn;          // 50176
constexpr int CHW = Cn * HW;
constexpr int NH  = Hn / WSz;         // 32
constexpr int NWb = NH * NH;          // 1024
constexpr int NWIN = Bn * NWb;        // 8192
constexpr int P   = WSz * WSz;        // 49
constexpr int MT  = Bn * HW;          // 401408

// ---------------- scratch ----------------
__device__ __align__(16) __half g_q [(size_t)NWIN * P * Cn];
__device__ __align__(16) __half g_k [(size_t)NWIN * P * Cn];
__device__ __align__(16) __half g_v [(size_t)NWIN * P * Cn];
__device__ __align__(16) __half g_whf[4][Cn * Cn];    // fp16 weights

// ---------------- helpers ----------------
__device__ __forceinline__ uint32_t sw128(uint32_t o) { return o ^ ((o >> 3) & 0x70); }

#define LDSM4(d0, d1, d2, d3, a) \
    asm volatile("ldmatrix.sync.aligned.m8n8.x4.shared.b16 {%0,%1,%2,%3},[%4];" \
        : "=r"(d0), "=r"(d1), "=r"(d2), "=r"(d3) : "r"(a))

#define MMA_F16(c, a, b) \
    asm volatile("mma.sync.aligned.m16n8k16.row.col.f32.f16.f16.f32 " \
        "{%0,%1,%2,%3},{%4,%5,%6,%7},{%8,%9},{%0,%1,%2,%3};" \
        : "+f"((c)[0]), "+f"((c)[1]), "+f"((c)[2]), "+f"((c)[3]) \
        : "r"((a)[0]), "r"((a)[1]), "r"((a)[2]), "r"((a)[3]), \
          "r"((b)[0]), "r"((b)[1]))

#define CP_ASYNC16(dst, src) \
    asm volatile("cp.async.ca.shared.global [%0],[%1],16;" :: "r"(dst), "l"(src))
#define CP_COMMIT()  asm volatile("cp.async.commit_group;" ::: "memory")
#define CP_WAIT1()   asm volatile("cp.async.wait_group 1;" ::: "memory")
#define CP_WAIT0()   asm volatile("cp.async.wait_group 0;" ::: "memory")

// =====================================================================
// prepass: weights -> fp16 once (tiny)
// =====================================================================
__global__ void k_prep_w(const float* __restrict__ Wq, const float* __restrict__ Wk,
                         const float* __restrict__ Wv, const float* __restrict__ Wo)
{
    int idx = blockIdx.x * 256 + threadIdx.x;
    int wsel = idx / (Cn * Cn);
    int r    = idx - wsel * (Cn * Cn);
    const float* W = (wsel == 0) ? Wq : (wsel == 1) ? Wk : (wsel == 2) ? Wv : Wo;
    g_whf[wsel][r] = __float2half_rn(W[r]);
}

// =====================================================================
// K1: single-pass fused QKV GEMM, all fp16 (FROZEN from round 11).
// =====================================================================
constexpr int Q3_A   = 0;          // 3 x 8192 = 24576
constexpr int Q3_B   = 24576;      // 2 x 24576 -> 73728
constexpr int Q3_BI  = 73728;      // 576 floats
constexpr int SMEM_QKV_BYTES = 73728 + 2304 + 128;

__global__ __launch_bounds__(256, 2) void k_qkv3(
    const float* __restrict__ x,
    const float* __restrict__ bq, const float* __restrict__ bk,
    const float* __restrict__ bv)
{
    extern __shared__ char smraw[];
    uint32_t sraw = (uint32_t)__cvta_generic_to_shared(smraw);
    const uint32_t s0 = (sraw + 127) & ~127u;
    char* sm = smraw + (s0 - sraw);
    float* sbias = (float*)(sm + Q3_BI);

    const int tid  = threadIdx.x;
    const int lane = tid & 31, wid = tid >> 5;
    const int wm   = wid >> 2, wn = wid & 3;
    const int m0   = blockIdx.x * 64;
    const int bb   = m0 / HW, rem0 = m0 - bb * HW;
    const float* xb = x + (size_t)bb * CHW + rem0;

    if (tid < 192) {
        sbias[tid]       = bq[tid];
        sbias[192 + tid] = bk[tid];
        sbias[384 + tid] = bv[tid];
    }

    const int lg = lane >> 3, lr = lane & 7;

    uint32_t offA[2][4], offB[3][4];
#pragma unroll
    for (int mt = 0; mt < 2; ++mt) {
        int row = wm * 32 + mt * 16 + ((lg & 1) << 3) + lr;
#pragma unroll
        for (int k8 = 0; k8 < 4; ++k8)
            offA[mt][k8] = sw128((uint32_t)(row * 128 + k8 * 32 + ((lg >> 1) << 4)));
    }
#pragma unroll
    for (int np = 0; np < 3; ++np) {
        int nr = wn * 48 + np * 16 + ((lg >> 1) << 3) + lr;
#pragma unroll
        for (int k8 = 0; k8 < 4; ++k8)
            offB[np][k8] = sw128((uint32_t)(nr * 128 + k8 * 32 + ((lg & 1) << 4)));
    }

    int scat[2][2];
#pragma unroll
    for (int mt = 0; mt < 2; ++mt)
#pragma unroll
        for (int hf = 0; hf < 2; ++hf) {
            int rem = rem0 + wm * 32 + mt * 16 + hf * 8 + (lane >> 2);
            int h = rem / Wn, w = rem - h * Wn;
            int hb = h / WSz, wb = w / WSz;
            int win = bb * NWb + hb * NH + wb;
            int pp  = (h - hb * WSz) * WSz + (w - wb * WSz);
            scat[mt][hf] = win * P + pp;
        }

    const int arow = tid & 63;
    const int aseg = tid >> 6;           // 0..3, 16 k each
    float areg[16];

    auto ldA = [&](int c) {
        const float* s = xb + (size_t)(c * 64 + aseg * 16) * HW + arow;
#pragma unroll
        for (int j = 0; j < 16; ++j) areg[j] = s[(size_t)j * HW];
    };
    auto stA = [&](int c) {
        char* ab = sm + Q3_A + c * 8192;
        uint32_t h[8];
#pragma unroll
        for (int q = 0; q < 8; ++q) {
            __half2 p = __floats2half2_rn(areg[2 * q], areg[2 * q + 1]);
            h[q] = *(uint32_t*)&p;
        }
        uint4 u0 = make_uint4(h[0], h[1], h[2], h[3]);
        uint4 u1 = make_uint4(h[4], h[5], h[6], h[7]);
        *(uint4*)(ab + sw128((uint32_t)(arow * 128 + aseg * 32)))      = u0;
        *(uint4*)(ab + sw128((uint32_t)(arow * 128 + aseg * 32 + 16))) = u1;
    };

    auto prefB = [&](int t) {            // t = wsel*3 + kt
        const __half* wsrc = g_whf[t / 3] + (t % 3) * 64;
        uint32_t bbf = s0 + Q3_B + (t & 1) * 24576;
#pragma unroll
        for (int i = 0; i < 6; ++i) {
            int ss = tid + i * 256;
            int bn = ss >> 3, bf = ss & 7;
            CP_ASYNC16(bbf + sw128((uint32_t)(bn * 128 + bf * 16)),
                       wsrc + (size_t)bn * Cn + bf * 8);
        }
    };

    float acc[2][6][4] = {};

    auto gemm_step = [&](uint32_t abase, uint32_t bbase) {
#pragma unroll
        for (int k8 = 0; k8 < 4; ++k8) {
            uint32_t af[2][4];
#pragma unroll
            for (int mt = 0; mt < 2; ++mt)
                LDSM4(af[mt][0], af[mt][1], af[mt][2], af[mt][3], abase + offA[mt][k8]);
            uint32_t bfr[6][2];
#pragma unroll
            for (int np = 0; np < 3; ++np)
                LDSM4(bfr[2 * np][0], bfr[2 * np][1], bfr[2 * np + 1][0], bfr[2 * np + 1][1],
                      bbase + offB[np][k8]);
#pragma unroll
            for (int mt = 0; mt < 2; ++mt)
#pragma unroll
                for (int nt = 0; nt < 6; ++nt)
                    MMA_F16(acc[mt][nt], af[mt], bfr[nt]);
        }
    };

    __half* dsts[3] = {g_q, g_k, g_v};
    auto do_epi = [&](int w) {
        __half* dst = dsts[w];
        const float* bofs = sbias + w * 192;
        const int col0 = wn * 48 + (lane & 3) * 2;
#pragma unroll
        for (int mt = 0; mt < 2; ++mt)
#pragma unroll
            for (int hf = 0; hf < 2; ++hf) {
                __half* dp = dst + (size_t)scat[mt][hf] * Cn;
#pragma unroll
                for (int nt = 0; nt < 6; ++nt) {
                    int c = col0 + nt * 8;
                    *(__half2*)(dp + c) = __floats2half2_rn(
                        acc[mt][nt][hf * 2 + 0] + bofs[c],
                        acc[mt][nt][hf * 2 + 1] + bofs[c + 1]);
                    acc[mt][nt][hf * 2 + 0] = 0.f;
                    acc[mt][nt][hf * 2 + 1] = 0.f;
                }
            }
    };

    ldA(0);
    prefB(0); CP_COMMIT();
    stA(0);
    ldA(1);
    __syncthreads();

#pragma unroll 3
    for (int t = 0; t < 9; ++t) {
        if (t < 8) { prefB(t + 1); CP_COMMIT(); CP_WAIT1(); }
        else       { CP_WAIT0(); }
        __syncthreads();
        if (t == 0) { stA(1); ldA(2); }
        if (t == 1) { stA(2); }
        gemm_step(s0 + Q3_A + (t - (t / 3) * 3) * 8192,
                  s0 + Q3_B + (t & 1) * 24576);
        __syncthreads();
        if (t == 2) do_epi(0);
        if (t == 5) do_epi(1);
    }
    do_epi(2);
}

// =====================================================================
// K2: FUSED attention + output projection (fp16 MMA, f32 accum).
//   128 threads (4 warps), one window per CTA.
//   Phases A/B/softmax identical to round-11 k_attn_mma; O kept in
//   smem (A-chunk fp16 layout); phase C: out = O @ Wo^T + bo, Wo tiles
//   double-buffered in the dead q/k region.
// smem map:
//   [0, 25088)      q/k double buf -> (B) vT@0 + P@12544 -> (C) Wo bufs
//   [25088, 42496)  S fp32          -> (B/C) O chunks 0,1 (8KB each)
//   [42496, 50688)  O chunk 2
//   [50688, 51456)  bias (192 f32)
// =====================================================================
constexpr int A_QB0 = 0;
constexpr int A_P   = 12544;
constexpr int A_VT  = 0;
constexpr int A_S   = 25088;
constexpr int F_O01 = 25088;      // chunks 0,1 (in dead S region)
constexpr int F_O2  = 42496;      // chunk 2
constexpr int F_BI  = 50688;
constexpr int SMEM_FUSED = 50688 + 768 + 128;   // 51584

__global__ __launch_bounds__(128, 4) void k_attn_oproj(
    const float* __restrict__ bo, float* __restrict__ out)
{
    extern __shared__ char smraw[];
    uint32_t sraw = (uint32_t)__cvta_generic_to_shared(smraw);
    const uint32_t s0 = (sraw + 127) & ~127u;
    char* sm = smraw + (s0 - sraw);

    const int tid  = threadIdx.x;
    const int lane = tid & 31, wm = tid >> 5;
    const int lg   = lane >> 3, lr = lane & 7;
    const int win  = blockIdx.x;

    const __half* qg = g_q + (size_t)win * P * Cn;
    const __half* kg = g_k + (size_t)win * P * Cn;
    const __half* vg = g_v + (size_t)win * P * Cn;
    float* sS    = (float*)(sm + A_S);
    float* sbias = (float*)(sm + F_BI);

    // load bias once (lives at F_BI, untouched by any phase)
    if (tid < 64) {
        sbias[tid]       = bo[tid];
        sbias[tid + 64]  = bo[tid + 64];
        sbias[tid + 128] = bo[tid + 128];
    }

    const int rowA      = wm * 16 + ((lg & 1) << 3) + lr;
    const uint32_t selA = (lg >> 1) << 4;
    const int nrb       = ((lg >> 1) << 3) + lr;
    const uint32_t selB = (lg & 1) << 4;

    // ---------------- Phase A: S = q k^T (identical to R11) ----------------
    auto prefQK = [&](int kt, int buf) {
        uint32_t qb = s0 + A_QB0 + buf * 12544;
        uint32_t kb = qb + 6272;
        for (int s = tid; s < 392; s += 128) {
            int row = s >> 3, f = s & 7;
            uint32_t o = sw128((uint32_t)(row * 128 + f * 16));
            CP_ASYNC16(qb + o, qg + (size_t)row * Cn + kt * 64 + f * 8);
            CP_ASYNC16(kb + o, kg + (size_t)row * Cn + kt * 64 + f * 8);
        }
    };

    {
        float acc[8][4] = {};
        prefQK(0, 0); CP_COMMIT();
        for (int kt = 0; kt < 3; ++kt) {
            const int cur = kt & 1;
            if (kt < 2) { prefQK(kt + 1, cur ^ 1); CP_COMMIT(); CP_WAIT1(); }
            else        { CP_WAIT0(); }
            __syncthreads();
            const uint32_t qb = s0 + A_QB0 + cur * 12544;
            const uint32_t kb = qb + 6272;
#pragma unroll
            for (int x = 0; x < 4; ++x) {
                uint32_t af[4];
                LDSM4(af[0], af[1], af[2], af[3],
                      qb + sw128((uint32_t)(rowA * 128 + x * 32) + selA));
                uint32_t bfr[8][2];
#pragma unroll
                for (int np = 0; np < 4; ++np) {
                    int nr = np * 16 + nrb;
                    LDSM4(bfr[2 * np][0], bfr[2 * np][1], bfr[2 * np + 1][0], bfr[2 * np + 1][1],
                          kb + sw128((uint32_t)(nr * 128 + x * 32) + selB));
                }
#pragma unroll
                for (int nt = 0; nt < 8; ++nt)
                    MMA_F16(acc[nt], af, bfr[nt]);
            }
            __syncthreads();
        }

        const float sc = 0.07216878364870323f;     // 1/sqrt(192)
        int rb = wm * 16 + (lane >> 2);
        int cb = (lane & 3) * 2;
#pragma unroll
        for (int hf = 0; hf < 2; ++hf) {
            int i = rb + hf * 8;
#pragma unroll
            for (int nt = 0; nt < 8; ++nt) {
                float2 v;
                v.x = acc[nt][hf * 2 + 0] * sc;
                v.y = acc[nt][hf * 2 + 1] * sc;
                *(float2*)(sS + i * 68 + nt * 8 + cb) = v;
            }
        }
    }
    __syncthreads();

    // ---------------- softmax (identical to R11) ----------------
    {
        const int row = tid >> 1, half = tid & 1;
        const bool valid = (row < P);
        float* r = sS + row * 68;
        char* pP = sm + A_P;
        float mx = -1e30f;
        if (valid)
            for (int j = half; j < P; j += 2) mx = fmaxf(mx, r[j]);
        mx = fmaxf(mx, __shfl_xor_sync(0xFFFFFFFFu, mx, 1));
        float sum = 0.f;
        float ev[25];
        int cnt = 0;
        if (valid)
            for (int j = half; j < P; j += 2) { float e = __expf(r[j] - mx); ev[cnt++] = e; sum += e; }
        sum += __shfl_xor_sync(0xFFFFFFFFu, sum, 1);
        if (valid) {
            float inv = 1.f / sum;
            cnt = 0;
            for (int j = half; j < P; j += 2)
                *(__half*)(pP + sw128((uint32_t)(row * 128 + j * 2))) =
                    __float2half_rn(ev[cnt++] * inv);
            for (int j = P + half; j < 64; j += 2)
                *(__half*)(pP + sw128((uint32_t)(row * 128 + j * 2))) = __float2half_rn(0.f);
        }
    }
    // zero vT pad k-columns (j=50..63) once
    {
        const __half2 z = __floats2half2_rn(0.f, 0.f);
        for (int s = tid; s < 448; s += 128) {
            int c = s / 7, jj = 50 + (s - (s / 7) * 7) * 2;
            *(__half2*)(sm + A_VT + sw128((uint32_t)(c * 128 + jj * 2))) = z;
        }
    }
    __syncthreads();
    // S region dead from here (probs live in P) -> reused for O chunks.

    // ---------------- Phase B: O = P @ V -> smem O chunks ----------------
    for (int cc = 0; cc < 3; ++cc) {
        if (cc > 0) __syncthreads();
        const int c0 = cc * 64;
        for (int s = tid; s < 200; s += 128) {
            int jp = s >> 3, cg = s & 7;
            int j0 = jp * 2;
            uint4 va = *(const uint4*)(vg + (size_t)j0 * Cn + c0 + cg * 8);
            uint4 vb = make_uint4(0u, 0u, 0u, 0u);
            if (j0 + 1 < P)
                vb = *(const uint4*)(vg + (size_t)(j0 + 1) * Cn + c0 + cg * 8);
            uint32_t ca[4] = {va.x, va.y, va.z, va.w};
            uint32_t cbu[4] = {vb.x, vb.y, vb.z, vb.w};
#pragma unroll
            for (int q = 0; q < 4; ++q) {
                __half2 ha = *(__half2*)&ca[q];
                __half2 hb = *(__half2*)&cbu[q];
                int c = cg * 8 + q * 2;
                *(__half2*)(sm + A_VT + sw128((uint32_t)(c * 128 + jp * 4)))       = __lows2half2(ha, hb);
                *(__half2*)(sm + A_VT + sw128((uint32_t)((c + 1) * 128 + jp * 4))) = __highs2half2(ha, hb);
            }
        }
        __syncthreads();

        float acc2[8][4] = {};
#pragma unroll
        for (int x = 0; x < 4; ++x) {
            uint32_t af[4];
            LDSM4(af[0], af[1], af[2], af[3],
                  s0 + A_P + sw128((uint32_t)(rowA * 128 + x * 32) + selA));
            uint32_t bfr[8][2];
#pragma unroll
            for (int np = 0; np < 4; ++np) {
                int nr = np * 16 + nrb;
                LDSM4(bfr[2 * np][0], bfr[2 * np][1], bfr[2 * np + 1][0], bfr[2 * np + 1][1],
                      s0 + A_VT + sw128((uint32_t)(nr * 128 + x * 32) + selB));
            }
#pragma unroll
            for (int nt = 0; nt < 8; ++nt)
                MMA_F16(acc2[nt], af, bfr[nt]);
        }

        // store O chunk cc (fp16, A-chunk layout; rows >=49 are finite
        // garbage, discarded by phase-C epilogue guard)
        char* ob = sm + (cc < 2 ? F_O01 + cc * 8192 : F_O2);
        int rb = wm * 16 + (lane >> 2);
        int cb = (lane & 3) * 2;
#pragma unroll
        for (int hf = 0; hf < 2; ++hf) {
            int i = rb + hf * 8;
#pragma unroll
            for (int nt = 0; nt < 8; ++nt) {
                int kk = nt * 8 + cb;     // 0..63 within chunk (even)
                *(__half2*)(ob + sw128((uint32_t)(i * 128 + kk * 2))) =
                    __floats2half2_rn(acc2[nt][hf * 2 + 0], acc2[nt][hf * 2 + 1]);
            }
        }
    }
    __syncthreads();   // O complete; vT/P dead -> q/k region free for Wo tiles

    // ---------------- Phase C: out = O @ Wo^T + bo ----------------
    const int bbw = win >> 10, wh = (win >> 5) & 31, ww = win & 31;

    auto prefC = [&](int t) {      // t = p*3 + kt ; Wo tile 96n x 64k = 12288B
        int p = t / 3, kt = t - p * 3;
        const __half* wsrc = g_whf[3] + (size_t)(p * 96) * Cn + kt * 64;
        uint32_t bbf = s0 + (t & 1) * 12288;
#pragma unroll
        for (int i = 0; i < 6; ++i) {
            int ss = tid + i * 128;
            int bn = ss >> 3, bf = ss & 7;
            CP_ASYNC16(bbf + sw128((uint32_t)(bn * 128 + bf * 16)),
                       wsrc + (size_t)bn * Cn + bf * 8);
        }
    };

    prefC(0); CP_COMMIT();

    float acc3[12][4] = {};
    for (int t = 0; t < 6; ++t) {
        if (t < 5) { prefC(t + 1); CP_COMMIT(); CP_WAIT1(); }
        else       { CP_WAIT0(); }
        __syncthreads();
        const int kt = t - (t / 3) * 3;
        const uint32_t abase = s0 + (kt < 2 ? F_O01 + kt * 8192 : F_O2);
        const uint32_t bbase = s0 + (t & 1) * 12288;
#pragma unroll
        for (int x = 0; x < 4; ++x) {
            uint32_t af[4];
            LDSM4(af[0], af[1], af[2], af[3],
                  abase + sw128((uint32_t)(rowA * 128 + x * 32) + selA));
            uint32_t bfr[12][2];
#pragma unroll
            for (int np = 0; np < 6; ++np) {
                int nr = np * 16 + nrb;
                LDSM4(bfr[2 * np][0], bfr[2 * np][1], bfr[2 * np + 1][0], bfr[2 * np + 1][1],
                      bbase + sw128((uint32_t)(nr * 128 + x * 32) + selB));
            }
#pragma unroll
            for (int nt = 0; nt < 12; ++nt)
                MMA_F16(acc3[nt], af, bfr[nt]);
        }
        __syncthreads();

        if (kt == 2) {
            const int p = t / 3;
            int rb = wm * 16 + (lane >> 2);
            int cb = (lane & 3) * 2;
#pragma unroll
            for (int hf = 0; hf < 2; ++hf) {
                int i = rb + hf * 8;
                if (i < P) {
                    int ph = i / WSz, pw = i - ph * WSz;
                    float* ob2 = out + (size_t)bbw * CHW +
                                 (size_t)(wh * WSz + ph) * Wn + ww * WSz + pw;
#pragma unroll
                    for (int nt = 0; nt < 12; ++nt) {
                        int n = p * 96 + nt * 8 + cb;
                        ob2[(size_t)n * HW]       = acc3[nt][hf * 2 + 0] + sbias[n];
                        ob2[(size_t)(n + 1) * HW] = acc3[nt][hf * 2 + 1] + sbias[n + 1];
                    }
                }
            }
#pragma unroll
            for (int nt = 0; nt < 12; ++nt)
#pragma unroll
                for (int j = 0; j < 4; ++j) acc3[nt][j] = 0.f;
        }
    }
}

// =====================================================================
extern "C" void kernel_launch(void* const* d_in, const int* in_sizes, int n_in,
                              void* d_out, int out_size)
{
    const float* x  = (const float*)d_in[0];
    const float* Wq = (const float*)d_in[1];
    const float* bq = (const float*)d_in[2];
    const float* Wk = (const float*)d_in[3];
    const float* bk = (const float*)d_in[4];
    const float* Wv = (const float*)d_in[5];
    const float* bv = (const float*)d_in[6];
    const float* Wo = (const float*)d_in[7];
    const float* bo = (const float*)d_in[8];
    float* out = (float*)d_out;

    cudaFuncSetAttribute(k_qkv3,       cudaFuncAttributeMaxDynamicSharedMemorySize, SMEM_QKV_BYTES);
    cudaFuncSetAttribute(k_attn_oproj, cudaFuncAttributeMaxDynamicSharedMemorySize, SMEM_FUSED);

    k_prep_w<<<(4 * Cn * Cn) / 256, 256>>>(Wq, Wk, Wv, Wo);

    k_qkv3<<<MT / 64, 256, SMEM_QKV_BYTES>>>(x, bq, bk, bv);

    k_attn_oproj<<<NWIN, 128, SMEM_FUSED>>>(bo, out);
}

// round 14
// speedup vs baseline: 1.2268x; 1.2268x over previous
#include <cuda_runtime.h>
#include <cuda_fp16.h>
#include <cstdint>

// ---------------- problem constants ----------------
constexpr int Bn  = 8;
constexpr int Cn  = 192;
constexpr int Hn  = 224;
constexpr int Wn  = 224;
constexpr int WSz = 7;
constexpr int HW  = Hn * Wn;          // 50176
constexpr int CHW = Cn * HW;
constexpr int NH  = Hn / WSz;         // 32
constexpr int NWb = NH * NH;          // 1024
constexpr int NWIN = Bn * NWb;        // 8192
constexpr int P   = WSz * WSz;        // 49
constexpr int MT  = Bn * HW;          // 401408

// ---------------- scratch ----------------
__device__ __align__(16) __half g_q [(size_t)NWIN * P * Cn];
__device__ __align__(16) __half g_k [(size_t)NWIN * P * Cn];
__device__ __align__(16) __half g_v [(size_t)NWIN * P * Cn];
__device__ __align__(16) __half g_ow[(size_t)MT * Cn];
__device__ __align__(16) __half g_whf[4][Cn * Cn];    // fp16 weights

// ---------------- helpers ----------------
__device__ __forceinline__ uint32_t sw128(uint32_t o) { return o ^ ((o >> 3) & 0x70); }

#define LDSM4(d0, d1, d2, d3, a) \
    asm volatile("ldmatrix.sync.aligned.m8n8.x4.shared.b16 {%0,%1,%2,%3},[%4];" \
        : "=r"(d0), "=r"(d1), "=r"(d2), "=r"(d3) : "r"(a))

#define MMA_F16(c, a, b) \
    asm volatile("mma.sync.aligned.m16n8k16.row.col.f32.f16.f16.f32 " \
        "{%0,%1,%2,%3},{%4,%5,%6,%7},{%8,%9},{%0,%1,%2,%3};" \
        : "+f"((c)[0]), "+f"((c)[1]), "+f"((c)[2]), "+f"((c)[3]) \
        : "r"((a)[0]), "r"((a)[1]), "r"((a)[2]), "r"((a)[3]), \
          "r"((b)[0]), "r"((b)[1]))

// L2-only cp.async: bypass L1 fill (all staged tiles are consumed from smem)
#define CP_ASYNC16(dst, src) \
    asm volatile("cp.async.cg.shared.global [%0],[%1],16;" :: "r"(dst), "l"(src))
#define CP_COMMIT()  asm volatile("cp.async.commit_group;" ::: "memory")
#define CP_WAIT1()   asm volatile("cp.async.wait_group 1;" ::: "memory")
#define CP_WAIT0()   asm volatile("cp.async.wait_group 0;" ::: "memory")

// =====================================================================
// prepass: weights -> fp16 once (tiny)
// =====================================================================
__global__ void k_prep_w(const float* __restrict__ Wq, const float* __restrict__ Wk,
                         const float* __restrict__ Wv, const float* __restrict__ Wo)
{
    int idx = blockIdx.x * 256 + threadIdx.x;
    int wsel = idx / (Cn * Cn);
    int r    = idx - wsel * (Cn * Cn);
    const float* W = (wsel == 0) ? Wq : (wsel == 1) ? Wk : (wsel == 2) ? Wv : Wo;
    g_whf[wsel][r] = __float2half_rn(W[r]);
}

// =====================================================================
// K1: single-pass fused QKV GEMM, all fp16 (m16n8k16, f32 accum).
// =====================================================================
constexpr int Q3_A   = 0;          // 3 x 8192 = 24576
constexpr int Q3_B   = 24576;      // 2 x 24576 -> 73728
constexpr int Q3_BI  = 73728;      // 576 floats
constexpr int SMEM_QKV_BYTES = 73728 + 2304 + 128;

__global__ __launch_bounds__(256, 2) void k_qkv3(
    const float* __restrict__ x,
    const float* __restrict__ bq, const float* __restrict__ bk,
    const float* __restrict__ bv)
{
    extern __shared__ char smraw[];
    uint32_t sraw = (uint32_t)__cvta_generic_to_shared(smraw);
    const uint32_t s0 = (sraw + 127) & ~127u;
    char* sm = smraw + (s0 - sraw);
    float* sbias = (float*)(sm + Q3_BI);

    const int tid  = threadIdx.x;
    const int lane = tid & 31, wid = tid >> 5;
    const int wm   = wid >> 2, wn = wid & 3;
    const int m0   = blockIdx.x * 64;
    const int bb   = m0 / HW, rem0 = m0 - bb * HW;
    const float* xb = x + (size_t)bb * CHW + rem0;

    if (tid < 192) {
        sbias[tid]       = bq[tid];
        sbias[192 + tid] = bk[tid];
        sbias[384 + tid] = bv[tid];
    }

    const int lg = lane >> 3, lr = lane & 7;

    uint32_t offA[2][4], offB[3][4];
#pragma unroll
    for (int mt = 0; mt < 2; ++mt) {
        int row = wm * 32 + mt * 16 + ((lg & 1) << 3) + lr;
#pragma unroll
        for (int k8 = 0; k8 < 4; ++k8)
            offA[mt][k8] = sw128((uint32_t)(row * 128 + k8 * 32 + ((lg >> 1) << 4)));
    }
#pragma unroll
    for (int np = 0; np < 3; ++np) {
        int nr = wn * 48 + np * 16 + ((lg >> 1) << 3) + lr;
#pragma unroll
        for (int k8 = 0; k8 < 4; ++k8)
            offB[np][k8] = sw128((uint32_t)(nr * 128 + k8 * 32 + ((lg & 1) << 4)));
    }

    int scat[2][2];
#pragma unroll
    for (int mt = 0; mt < 2; ++mt)
#pragma unroll
        for (int hf = 0; hf < 2; ++hf) {
            int rem = rem0 + wm * 32 + mt * 16 + hf * 8 + (lane >> 2);
            int h = rem / Wn, w = rem - h * Wn;
            int hb = h / WSz, wb = w / WSz;
            int win = bb * NWb + hb * NH + wb;
            int pp  = (h - hb * WSz) * WSz + (w - wb * WSz);
            scat[mt][hf] = win * P + pp;
        }

    const int arow = tid & 63;
    const int aseg = tid >> 6;           // 0..3, 16 k each
    float areg[16];

    auto ldA = [&](int c) {
        const float* s = xb + (size_t)(c * 64 + aseg * 16) * HW + arow;
#pragma unroll
        for (int j = 0; j < 16; ++j) areg[j] = s[(size_t)j * HW];
    };
    auto stA = [&](int c) {
        char* ab = sm + Q3_A + c * 8192;
        uint32_t h[8];
#pragma unroll
        for (int q = 0; q < 8; ++q) {
            __half2 p = __floats2half2_rn(areg[2 * q], areg[2 * q + 1]);
            h[q] = *(uint32_t*)&p;
        }
        uint4 u0 = make_uint4(h[0], h[1], h[2], h[3]);
        uint4 u1 = make_uint4(h[4], h[5], h[6], h[7]);
        *(uint4*)(ab + sw128((uint32_t)(arow * 128 + aseg * 32)))      = u0;
        *(uint4*)(ab + sw128((uint32_t)(arow * 128 + aseg * 32 + 16))) = u1;
    };

    auto prefB = [&](int t) {            // t = wsel*3 + kt
        const __half* wsrc = g_whf[t / 3] + (t % 3) * 64;
        uint32_t bbf = s0 + Q3_B + (t & 1) * 24576;
#pragma unroll
        for (int i = 0; i < 6; ++i) {
            int ss = tid + i * 256;
            int bn = ss >> 3, bf = ss & 7;
            CP_ASYNC16(bbf + sw128((uint32_t)(bn * 128 + bf * 16)),
                       wsrc + (size_t)bn * Cn + bf * 8);
        }
    };

    float acc[2][6][4] = {};

    auto gemm_step = [&](uint32_t abase, uint32_t bbase) {
#pragma unroll
        for (int k8 = 0; k8 < 4; ++k8) {
            uint32_t af[2][4];
#pragma unroll
            for (int mt = 0; mt < 2; ++mt)
                LDSM4(af[mt][0], af[mt][1], af[mt][2], af[mt][3], abase + offA[mt][k8]);
            uint32_t bfr[6][2];
#pragma unroll
            for (int np = 0; np < 3; ++np)
                LDSM4(bfr[2 * np][0], bfr[2 * np][1], bfr[2 * np + 1][0], bfr[2 * np + 1][1],
                      bbase + offB[np][k8]);
#pragma unroll
            for (int mt = 0; mt < 2; ++mt)
#pragma unroll
                for (int nt = 0; nt < 6; ++nt)
                    MMA_F16(acc[mt][nt], af[mt], bfr[nt]);
        }
    };

    __half* dsts[3] = {g_q, g_k, g_v};
    auto do_epi = [&](int w) {
        __half* dst = dsts[w];
        const float* bofs = sbias + w * 192;
        const int col0 = wn * 48 + (lane & 3) * 2;
#pragma unroll
        for (int mt = 0; mt < 2; ++mt)
#pragma unroll
            for (int hf = 0; hf < 2; ++hf) {
                __half* dp = dst + (size_t)scat[mt][hf] * Cn;
#pragma unroll
                for (int nt = 0; nt < 6; ++nt) {
                    int c = col0 + nt * 8;
                    *(__half2*)(dp + c) = __floats2half2_rn(
                        acc[mt][nt][hf * 2 + 0] + bofs[c],
                        acc[mt][nt][hf * 2 + 1] + bofs[c + 1]);
                    acc[mt][nt][hf * 2 + 0] = 0.f;
                    acc[mt][nt][hf * 2 + 1] = 0.f;
                }
            }
    };

    ldA(0);
    prefB(0); CP_COMMIT();
    stA(0);
    ldA(1);
    __syncthreads();

#pragma unroll 3
    for (int t = 0; t < 9; ++t) {
        if (t < 8) { prefB(t + 1); CP_COMMIT(); CP_WAIT1(); }
        else       { CP_WAIT0(); }
        __syncthreads();
        if (t == 0) { stA(1); ldA(2); }
        if (t == 1) { stA(2); }
        gemm_step(s0 + Q3_A + (t - (t / 3) * 3) * 8192,
                  s0 + Q3_B + (t & 1) * 24576);
        __syncthreads();
        if (t == 2) do_epi(0);
        if (t == 5) do_epi(1);
    }
    do_epi(2);
}

// =====================================================================
// K3: output projection GEMM, all fp16 (A = g_ow fp16, B = Wo fp16).
// =====================================================================
constexpr int GOFF_A  = 0;          // 2 x 8192
constexpr int GOFF_B  = 16384;      // 2 x 24576 -> 65536
constexpr int GOFF_BI = 65536;
constexpr int SMEM_GEMM_BYTES = 65536 + 768 + 128;

__global__ __launch_bounds__(256, 2) void k_oproj_mma(
    const float* __restrict__ bo, float* __restrict__ out)
{
    extern __shared__ char smraw[];
    uint32_t sraw = (uint32_t)__cvta_generic_to_shared(smraw);
    const uint32_t s0 = (sraw + 127) & ~127u;
    char* sm = smraw + (s0 - sraw);
    float* sbias = (float*)(sm + GOFF_BI);

    const int tid  = threadIdx.x;
    const int lane = tid & 31, wid = tid >> 5;
    const int wm   = wid >> 2, wn = wid & 3;
    const int m0   = blockIdx.x * 64;
    const int bb   = m0 / HW, rem0 = m0 - bb * HW;
    const __half* Wt = g_whf[3];

    if (tid < 192) sbias[tid] = bo[tid];

    const int lg = lane >> 3, lr = lane & 7;

    uint32_t offA[2][4], offB[3][4];
#pragma unroll
    for (int mt = 0; mt < 2; ++mt) {
        int row = wm * 32 + mt * 16 + ((lg & 1) << 3) + lr;
#pragma unroll
        for (int k8 = 0; k8 < 4; ++k8)
            offA[mt][k8] = sw128((uint32_t)(row * 128 + k8 * 32 + ((lg >> 1) << 4)));
    }
#pragma unroll
    for (int np = 0; np < 3; ++np) {
        int nr = wn * 48 + np * 16 + ((lg >> 1) << 3) + lr;
#pragma unroll
        for (int k8 = 0; k8 < 4; ++k8)
            offB[np][k8] = sw128((uint32_t)(nr * 128 + k8 * 32 + ((lg & 1) << 4)));
    }

    float acc[2][6][4] = {};

    auto prefetch = [&](int kt, int buf) {
        uint32_t ab  = s0 + GOFF_A + buf * 8192;
        uint32_t bbf = s0 + GOFF_B + buf * 24576;
        {
            int r = tid >> 2, f = tid & 3;
            CP_ASYNC16(ab + sw128((uint32_t)(r * 128 + f * 32)),
                       g_ow + (size_t)(m0 + r) * Cn + kt * 64 + f * 16);
            CP_ASYNC16(ab + sw128((uint32_t)(r * 128 + f * 32 + 16)),
                       g_ow + (size_t)(m0 + r) * Cn + kt * 64 + f * 16 + 8);
        }
        const __half* wsrc = Wt + kt * 64;
#pragma unroll
        for (int i = 0; i < 6; ++i) {
            int ss = tid + i * 256;
            int bn = ss >> 3, bf = ss & 7;
            CP_ASYNC16(bbf + sw128((uint32_t)(bn * 128 + bf * 16)),
                       wsrc + (size_t)bn * Cn + bf * 8);
        }
    };

    prefetch(0, 0); CP_COMMIT();
    for (int kt = 0; kt < 3; ++kt) {
        const int cur = kt & 1;
        if (kt < 2) { prefetch(kt + 1, cur ^ 1); CP_COMMIT(); CP_WAIT1(); }
        else        { CP_WAIT0(); }
        __syncthreads();
        const uint32_t abase = s0 + GOFF_A + cur * 8192;
        const uint32_t bbase = s0 + GOFF_B + cur * 24576;
#pragma unroll
        for (int k8 = 0; k8 < 4; ++k8) {
            uint32_t af[2][4];
#pragma unroll
            for (int mt = 0; mt < 2; ++mt)
                LDSM4(af[mt][0], af[mt][1], af[mt][2], af[mt][3], abase + offA[mt][k8]);
            uint32_t bfr[6][2];
#pragma unroll
            for (int np = 0; np < 3; ++np)
                LDSM4(bfr[2 * np][0], bfr[2 * np][1], bfr[2 * np + 1][0], bfr[2 * np + 1][1],
                      bbase + offB[np][k8]);
#pragma unroll
            for (int mt = 0; mt < 2; ++mt)
#pragma unroll
                for (int nt = 0; nt < 6; ++nt)
                    MMA_F16(acc[mt][nt], af[mt], bfr[nt]);
        }
        __syncthreads();
    }

    const int col0 = wn * 48 + (lane & 3) * 2;
    float* ob = out + (size_t)bb * CHW;
#pragma unroll
    for (int mt = 0; mt < 2; ++mt)
#pragma unroll
        for (int hf = 0; hf < 2; ++hf) {
            int rem = rem0 + wm * 32 + mt * 16 + hf * 8 + (lane >> 2);
#pragma unroll
            for (int nt = 0; nt < 6; ++nt) {
#pragma unroll
                for (int j = 0; j < 2; ++j) {
                    int c = col0 + nt * 8 + j;
                    ob[(size_t)c * HW + rem] = acc[mt][nt][hf * 2 + j] + sbias[c];
                }
            }
        }
}

// =====================================================================
// K2: per-window attention, fp16 (round-11 structure).
// =====================================================================
constexpr int A_QB0 = 0;
constexpr int A_P   = 12544;
constexpr int A_VT  = 0;
constexpr int A_S   = 25088;
constexpr int SMEM_ATTN_BYTES = 25088 + 17408 + 128;   // 42624

__global__ __launch_bounds__(128, 5) void k_attn_mma()
{
    extern __shared__ char smraw[];
    uint32_t sraw = (uint32_t)__cvta_generic_to_shared(smraw);
    const uint32_t s0 = (sraw + 127) & ~127u;
    char* sm = smraw + (s0 - sraw);

    const int tid  = threadIdx.x;
    const int lane = tid & 31, wm = tid >> 5;
    const int lg   = lane >> 3, lr = lane & 7;
    const int win  = blockIdx.x;

    const __half* qg = g_q + (size_t)win * P * Cn;
    const __half* kg = g_k + (size_t)win * P * Cn;
    const __half* vg = g_v + (size_t)win * P * Cn;
    float* sS = (float*)(sm + A_S);

    const int rowA      = wm * 16 + ((lg & 1) << 3) + lr;
    const uint32_t selA = (lg >> 1) << 4;
    const int nrb       = ((lg >> 1) << 3) + lr;
    const uint32_t selB = (lg & 1) << 4;

    auto prefQK = [&](int kt, int buf) {
        uint32_t qb = s0 + A_QB0 + buf * 12544;
        uint32_t kb = qb + 6272;
        for (int s = tid; s < 392; s += 128) {
            int row = s >> 3, f = s & 7;
            uint32_t o = sw128((uint32_t)(row * 128 + f * 16));
            CP_ASYNC16(qb + o, qg + (size_t)row * Cn + kt * 64 + f * 8);
            CP_ASYNC16(kb + o, kg + (size_t)row * Cn + kt * 64 + f * 8);
        }
    };

    float acc[8][4] = {};
    prefQK(0, 0); CP_COMMIT();
    for (int kt = 0; kt < 3; ++kt) {
        const int cur = kt & 1;
        if (kt < 2) { prefQK(kt + 1, cur ^ 1); CP_COMMIT(); CP_WAIT1(); }
        else        { CP_WAIT0(); }
        __syncthreads();
        const uint32_t qb = s0 + A_QB0 + cur * 12544;
        const uint32_t kb = qb + 6272;
#pragma unroll
        for (int x = 0; x < 4; ++x) {
            uint32_t af[4];
            LDSM4(af[0], af[1], af[2], af[3],
                  qb + sw128((uint32_t)(rowA * 128 + x * 32) + selA));
            uint32_t bfr[8][2];
#pragma unroll
            for (int np = 0; np < 4; ++np) {
                int nr = np * 16 + nrb;
                LDSM4(bfr[2 * np][0], bfr[2 * np][1], bfr[2 * np + 1][0], bfr[2 * np + 1][1],
                      kb + sw128((uint32_t)(nr * 128 + x * 32) + selB));
            }
#pragma unroll
            for (int nt = 0; nt < 8; ++nt)
                MMA_F16(acc[nt], af, bfr[nt]);
        }
        __syncthreads();
    }

    const float sc = 0.07216878364870323f;     // 1/sqrt(192)
    {
        int rb = wm * 16 + (lane >> 2);
        int cb = (lane & 3) * 2;
#pragma unroll
        for (int hf = 0; hf < 2; ++hf) {
            int i = rb + hf * 8;
#pragma unroll
            for (int nt = 0; nt < 8; ++nt) {
                float2 v;
                v.x = acc[nt][hf * 2 + 0] * sc;
                v.y = acc[nt][hf * 2 + 1] * sc;
                *(float2*)(sS + i * 68 + nt * 8 + cb) = v;
            }
        }
    }
    __syncthreads();

    // softmax (2 threads/row, full-warp shfl); probs -> fp16 P buffer
    {
        const int row = tid >> 1, half = tid & 1;
        const bool valid = (row < P);
        float* r = sS + row * 68;
        char* pP = sm + A_P;
        float mx = -1e30f;
        if (valid)
            for (int j = half; j < P; j += 2) mx = fmaxf(mx, r[j]);
        mx = fmaxf(mx, __shfl_xor_sync(0xFFFFFFFFu, mx, 1));
        float sum = 0.f;
        float ev[25];
        int cnt = 0;
        if (valid)
            for (int j = half; j < P; j += 2) { float e = __expf(r[j] - mx); ev[cnt++] = e; sum += e; }
        sum += __shfl_xor_sync(0xFFFFFFFFu, sum, 1);
        if (valid) {
            float inv = 1.f / sum;
            cnt = 0;
            for (int j = half; j < P; j += 2)
                *(__half*)(pP + sw128((uint32_t)(row * 128 + j * 2))) =
                    __float2half_rn(ev[cnt++] * inv);
            for (int j = P + half; j < 64; j += 2)
                *(__half*)(pP + sw128((uint32_t)(row * 128 + j * 2))) = __float2half_rn(0.f);
        }
    }
    // zero vT pad k-columns (j=50..63) once
    {
        const __half2 z = __floats2half2_rn(0.f, 0.f);
        for (int s = tid; s < 448; s += 128) {
            int c = s / 7, jj = 50 + (s - (s / 7) * 7) * 2;
            *(__half2*)(sm + A_VT + sw128((uint32_t)(c * 128 + jj * 2))) = z;
        }
    }
    __syncthreads();

    // Phase B: O = P @ V, 3 chunks of 64 channels
    const int bbw = win >> 10, wh = (win >> 5) & 31, ww = win & 31;
    for (int cc = 0; cc < 3; ++cc) {
        if (cc > 0) __syncthreads();
        const int c0 = cc * 64;
        for (int s = tid; s < 200; s += 128) {
            int jp = s >> 3, cg = s & 7;
            int j0 = jp * 2;
            uint4 va = *(const uint4*)(vg + (size_t)j0 * Cn + c0 + cg * 8);
            uint4 vb = make_uint4(0u, 0u, 0u, 0u);
            if (j0 + 1 < P)
                vb = *(const uint4*)(vg + (size_t)(j0 + 1) * Cn + c0 + cg * 8);
            uint32_t ca[4] = {va.x, va.y, va.z, va.w};
            uint32_t cbu[4] = {vb.x, vb.y, vb.z, vb.w};
#pragma unroll
            for (int q = 0; q < 4; ++q) {
                __half2 ha = *(__half2*)&ca[q];
                __half2 hb = *(__half2*)&cbu[q];
                int c = cg * 8 + q * 2;
                *(__half2*)(sm + A_VT + sw128((uint32_t)(c * 128 + jp * 4)))       = __lows2half2(ha, hb);
                *(__half2*)(sm + A_VT + sw128((uint32_t)((c + 1) * 128 + jp * 4))) = __highs2half2(ha, hb);
            }
        }
        __syncthreads();

        float acc2[8][4] = {};
#pragma unroll
        for (int x = 0; x < 4; ++x) {
            uint32_t af[4];
            LDSM4(af[0], af[1], af[2], af[3],
                  s0 + A_P + sw128((uint32_t)(rowA * 128 + x * 32) + selA));
            uint32_t bfr[8][2];
#pragma unroll
            for (int np = 0; np < 4; ++np) {
                int nr = np * 16 + nrb;
                LDSM4(bfr[2 * np][0], bfr[2 * np][1], bfr[2 * np + 1][0], bfr[2 * np + 1][1],
                      s0 + A_VT + sw128((uint32_t)(nr * 128 + x * 32) + selB));
            }
#pragma unroll
            for (int nt = 0; nt < 8; ++nt)
                MMA_F16(acc2[nt], af, bfr[nt]);
        }

        int rb = wm * 16 + (lane >> 2);
        int cb = (lane & 3) * 2;
#pragma unroll
        for (int hf = 0; hf < 2; ++hf) {
            int i = rb + hf * 8;
            if (i < P) {
                int ph = i / WSz, pw = i - ph * WSz;
                int m = bbw * HW + (wh * WSz + ph) * Wn + ww * WSz + pw;
                __half* op = g_ow + (size_t)m * Cn + c0 + cb;
#pragma unroll
                for (int nt = 0; nt < 8; ++nt)
                    *(__half2*)(op + nt * 8) = __floats2half2_rn(
                        acc2[nt][hf * 2 + 0], acc2[nt][hf * 2 + 1]);
            }
        }
    }
}

// =====================================================================
extern "C" void kernel_launch(void* const* d_in, const int* in_sizes, int n_in,
                              void* d_out, int out_size)
{
    const float* x  = (const float*)d_in[0];
    const float* Wq = (const float*)d_in[1];
    const float* bq = (const float*)d_in[2];
    const float* Wk = (const float*)d_in[3];
    const float* bk = (const float*)d_in[4];
    const float* Wv = (const float*)d_in[5];
    const float* bv = (const float*)d_in[6];
    const float* Wo = (const float*)d_in[7];
    const float* bo = (const float*)d_in[8];
    float* out = (float*)d_out;

    cudaFuncSetAttribute(k_qkv3,      cudaFuncAttributeMaxDynamicSharedMemorySize, SMEM_QKV_BYTES);
    cudaFuncSetAttribute(k_oproj_mma, cudaFuncAttributeMaxDynamicSharedMemorySize, SMEM_GEMM_BYTES);
    cudaFuncSetAttribute(k_attn_mma,  cudaFuncAttributeMaxDynamicSharedMemorySize, SMEM_ATTN_BYTES);

    k_prep_w<<<(4 * Cn * Cn) / 256, 256>>>(Wq, Wk, Wv, Wo);

    k_qkv3<<<MT / 64, 256, SMEM_QKV_BYTES>>>(x, bq, bk, bv);

    k_attn_mma<<<NWIN, 128, SMEM_ATTN_BYTES>>>();

    k_oproj_mma<<<MT / 64, 256, SMEM_GEMM_BYTES>>>(bo, out);
}

// round 15
// speedup vs baseline: 1.2322x; 1.0044x over previous
#include <cuda_runtime.h>
#include <cuda_fp16.h>
#include <cstdint>

// ---------------- problem constants ----------------
constexpr int Bn  = 8;
constexpr int Cn  = 192;
constexpr int Hn  = 224;
constexpr int Wn  = 224;
constexpr int WSz = 7;
constexpr int HW  = Hn * Wn;          // 50176
constexpr int CHW = Cn * HW;
constexpr int NH  = Hn / WSz;         // 32
constexpr int NWb = NH * NH;          // 1024
constexpr int NWIN = Bn * NWb;        // 8192
constexpr int P   = WSz * WSz;        // 49
constexpr int MT  = Bn * HW;          // 401408

// ---------------- scratch ----------------
__device__ __align__(16) __half g_q [(size_t)NWIN * P * Cn];
__device__ __align__(16) __half g_k [(size_t)NWIN * P * Cn];
__device__ __align__(16) __half g_v [(size_t)NWIN * P * Cn];
__device__ __align__(16) __half g_ow[(size_t)MT * Cn];
__device__ __align__(16) __half g_whf[4][Cn * Cn];    // fp16 weights

// ---------------- helpers ----------------
__device__ __forceinline__ uint32_t sw128(uint32_t o) { return o ^ ((o >> 3) & 0x70); }

#define LDSM4(d0, d1, d2, d3, a) \
    asm volatile("ldmatrix.sync.aligned.m8n8.x4.shared.b16 {%0,%1,%2,%3},[%4];" \
        : "=r"(d0), "=r"(d1), "=r"(d2), "=r"(d3) : "r"(a))

#define MMA_F16(c, a, b) \
    asm volatile("mma.sync.aligned.m16n8k16.row.col.f32.f16.f16.f32 " \
        "{%0,%1,%2,%3},{%4,%5,%6,%7},{%8,%9},{%0,%1,%2,%3};" \
        : "+f"((c)[0]), "+f"((c)[1]), "+f"((c)[2]), "+f"((c)[3]) \
        : "r"((a)[0]), "r"((a)[1]), "r"((a)[2]), "r"((a)[3]), \
          "r"((b)[0]), "r"((b)[1]))

// L2-only cp.async (R14 win)
#define CP_ASYNC16(dst, src) \
    asm volatile("cp.async.cg.shared.global [%0],[%1],16;" :: "r"(dst), "l"(src))
#define CP_COMMIT()  asm volatile("cp.async.commit_group;" ::: "memory")
#define CP_WAIT2()   asm volatile("cp.async.wait_group 2;" ::: "memory")
#define CP_WAIT1()   asm volatile("cp.async.wait_group 1;" ::: "memory")
#define CP_WAIT0()   asm volatile("cp.async.wait_group 0;" ::: "memory")

// =====================================================================
// prepass: weights -> fp16 once (tiny)
// =====================================================================
__global__ void k_prep_w(const float* __restrict__ Wq, const float* __restrict__ Wk,
                         const float* __restrict__ Wv, const float* __restrict__ Wo)
{
    int idx = blockIdx.x * 256 + threadIdx.x;
    int wsel = idx / (Cn * Cn);
    int r    = idx - wsel * (Cn * Cn);
    const float* W = (wsel == 0) ? Wq : (wsel == 1) ? Wk : (wsel == 2) ? Wv : Wo;
    g_whf[wsel][r] = __float2half_rn(W[r]);
}

// =====================================================================
// K1: single-pass fused QKV GEMM, all fp16.
//   B TRIPLE-buffered, prefetch distance 2, ONE sync per step.
// =====================================================================
constexpr int Q3_A   = 0;          // 3 x 8192 = 24576
constexpr int Q3_B   = 24576;      // 3 x 24576 -> 98304
constexpr int Q3_BI  = 98304;      // 576 floats
constexpr int SMEM_QKV_BYTES = 98304 + 2304 + 128;   // 100736

__global__ __launch_bounds__(256, 2) void k_qkv3(
    const float* __restrict__ x,
    const float* __restrict__ bq, const float* __restrict__ bk,
    const float* __restrict__ bv)
{
    extern __shared__ char smraw[];
    uint32_t sraw = (uint32_t)__cvta_generic_to_shared(smraw);
    const uint32_t s0 = (sraw + 127) & ~127u;
    char* sm = smraw + (s0 - sraw);
    float* sbias = (float*)(sm + Q3_BI);

    const int tid  = threadIdx.x;
    const int lane = tid & 31, wid = tid >> 5;
    const int wm   = wid >> 2, wn = wid & 3;
    const int m0   = blockIdx.x * 64;
    const int bb   = m0 / HW, rem0 = m0 - bb * HW;
    const float* xb = x + (size_t)bb * CHW + rem0;

    if (tid < 192) {
        sbias[tid]       = bq[tid];
        sbias[192 + tid] = bk[tid];
        sbias[384 + tid] = bv[tid];
    }

    const int lg = lane >> 3, lr = lane & 7;

    uint32_t offA[2][4], offB[3][4];
#pragma unroll
    for (int mt = 0; mt < 2; ++mt) {
        int row = wm * 32 + mt * 16 + ((lg & 1) << 3) + lr;
#pragma unroll
        for (int k8 = 0; k8 < 4; ++k8)
            offA[mt][k8] = sw128((uint32_t)(row * 128 + k8 * 32 + ((lg >> 1) << 4)));
    }
#pragma unroll
    for (int np = 0; np < 3; ++np) {
        int nr = wn * 48 + np * 16 + ((lg >> 1) << 3) + lr;
#pragma unroll
        for (int k8 = 0; k8 < 4; ++k8)
            offB[np][k8] = sw128((uint32_t)(nr * 128 + k8 * 32 + ((lg & 1) << 4)));
    }

    int scat[2][2];
#pragma unroll
    for (int mt = 0; mt < 2; ++mt)
#pragma unroll
        for (int hf = 0; hf < 2; ++hf) {
            int rem = rem0 + wm * 32 + mt * 16 + hf * 8 + (lane >> 2);
            int h = rem / Wn, w = rem - h * Wn;
            int hb = h / WSz, wb = w / WSz;
            int win = bb * NWb + hb * NH + wb;
            int pp  = (h - hb * WSz) * WSz + (w - wb * WSz);
            scat[mt][hf] = win * P + pp;
        }

    const int arow = tid & 63;
    const int aseg = tid >> 6;           // 0..3, 16 k each
    float areg[16];

    auto ldA = [&](int c) {
        const float* s = xb + (size_t)(c * 64 + aseg * 16) * HW + arow;
#pragma unroll
        for (int j = 0; j < 16; ++j) areg[j] = s[(size_t)j * HW];
    };
    auto stA = [&](int c) {
        char* ab = sm + Q3_A + c * 8192;
        uint32_t h[8];
#pragma unroll
        for (int q = 0; q < 8; ++q) {
            __half2 p = __floats2half2_rn(areg[2 * q], areg[2 * q + 1]);
            h[q] = *(uint32_t*)&p;
        }
        uint4 u0 = make_uint4(h[0], h[1], h[2], h[3]);
        uint4 u1 = make_uint4(h[4], h[5], h[6], h[7]);
        *(uint4*)(ab + sw128((uint32_t)(arow * 128 + aseg * 32)))      = u0;
        *(uint4*)(ab + sw128((uint32_t)(arow * 128 + aseg * 32 + 16))) = u1;
    };

    auto prefB = [&](int t) {            // t = wsel*3 + kt ; buffer t%3
        const __half* wsrc = g_whf[t / 3] + (t % 3) * 64;
        uint32_t bbf = s0 + Q3_B + (t % 3) * 24576;
#pragma unroll
        for (int i = 0; i < 6; ++i) {
            int ss = tid + i * 256;
            int bn = ss >> 3, bf = ss & 7;
            CP_ASYNC16(bbf + sw128((uint32_t)(bn * 128 + bf * 16)),
                       wsrc + (size_t)bn * Cn + bf * 8);
        }
    };

    float acc[2][6][4] = {};

    auto gemm_step = [&](uint32_t abase, uint32_t bbase) {
#pragma unroll
        for (int k8 = 0; k8 < 4; ++k8) {
            uint32_t af[2][4];
#pragma unroll
            for (int mt = 0; mt < 2; ++mt)
                LDSM4(af[mt][0], af[mt][1], af[mt][2], af[mt][3], abase + offA[mt][k8]);
            uint32_t bfr[6][2];
#pragma unroll
            for (int np = 0; np < 3; ++np)
                LDSM4(bfr[2 * np][0], bfr[2 * np][1], bfr[2 * np + 1][0], bfr[2 * np + 1][1],
                      bbase + offB[np][k8]);
#pragma unroll
            for (int mt = 0; mt < 2; ++mt)
#pragma unroll
                for (int nt = 0; nt < 6; ++nt)
                    MMA_F16(acc[mt][nt], af[mt], bfr[nt]);
        }
    };

    __half* dsts[3] = {g_q, g_k, g_v};
    auto do_epi = [&](int w) {
        __half* dst = dsts[w];
        const float* bofs = sbias + w * 192;
        const int col0 = wn * 48 + (lane & 3) * 2;
#pragma unroll
        for (int mt = 0; mt < 2; ++mt)
#pragma unroll
            for (int hf = 0; hf < 2; ++hf) {
                __half* dp = dst + (size_t)scat[mt][hf] * Cn;
#pragma unroll
                for (int nt = 0; nt < 6; ++nt) {
                    int c = col0 + nt * 8;
                    *(__half2*)(dp + c) = __floats2half2_rn(
                        acc[mt][nt][hf * 2 + 0] + bofs[c],
                        acc[mt][nt][hf * 2 + 1] + bofs[c + 1]);
                    acc[mt][nt][hf * 2 + 0] = 0.f;
                    acc[mt][nt][hf * 2 + 1] = 0.f;
                }
            }
    };

    // prologue: A chunk 0 staged; chunk-1 LDGs in flight; B(0), B(1) queued
    ldA(0);
    prefB(0); CP_COMMIT();
    prefB(1); CP_COMMIT();
    stA(0);
    ldA(1);

    // t = wsel*3 + kt, t = 0..8 ; ONE sync per step
#pragma unroll 3
    for (int t = 0; t < 9; ++t) {
        if (t < 7)      CP_WAIT1();    // groups t+1 (and t+2 after issue) allowed
        else if (t < 8) CP_WAIT1();
        else            CP_WAIT0();
        __syncthreads();               // B(t) + A-chunk visibility; frees buf (t+2)%3
        if (t < 7) { prefB(t + 2); CP_COMMIT(); }
        if (t == 0) { stA(1); ldA(2); }
        if (t == 1) { stA(2); }
        gemm_step(s0 + Q3_A + (t - (t / 3) * 3) * 8192,
                  s0 + Q3_B + (t % 3) * 24576);
        if ((t - (t / 3) * 3) == 2) do_epi(t / 3);
    }
}

// =====================================================================
// K3: output projection GEMM, all fp16.
//   All 3 chunks prefetched up front (A+B triple-buffered),
//   ONE sync per step.
// =====================================================================
constexpr int GOFF_A  = 0;          // 3 x 8192 = 24576
constexpr int GOFF_B  = 24576;      // 3 x 24576 -> 98304
constexpr int GOFF_BI = 98304;
constexpr int SMEM_GEMM_BYTES = 98304 + 768 + 128;

__global__ __launch_bounds__(256, 2) void k_oproj_mma(
    const float* __restrict__ bo, float* __restrict__ out)
{
    extern __shared__ char smraw[];
    uint32_t sraw = (uint32_t)__cvta_generic_to_shared(smraw);
    const uint32_t s0 = (sraw + 127) & ~127u;
    char* sm = smraw + (s0 - sraw);
    float* sbias = (float*)(sm + GOFF_BI);

    const int tid  = threadIdx.x;
    const int lane = tid & 31, wid = tid >> 5;
    const int wm   = wid >> 2, wn = wid & 3;
    const int m0   = blockIdx.x * 64;
    const int bb   = m0 / HW, rem0 = m0 - bb * HW;
    const __half* Wt = g_whf[3];

    if (tid < 192) sbias[tid] = bo[tid];

    const int lg = lane >> 3, lr = lane & 7;

    uint32_t offA[2][4], offB[3][4];
#pragma unroll
    for (int mt = 0; mt < 2; ++mt) {
        int row = wm * 32 + mt * 16 + ((lg & 1) << 3) + lr;
#pragma unroll
        for (int k8 = 0; k8 < 4; ++k8)
            offA[mt][k8] = sw128((uint32_t)(row * 128 + k8 * 32 + ((lg >> 1) << 4)));
    }
#pragma unroll
    for (int np = 0; np < 3; ++np) {
        int nr = wn * 48 + np * 16 + ((lg >> 1) << 3) + lr;
#pragma unroll
        for (int k8 = 0; k8 < 4; ++k8)
            offB[np][k8] = sw128((uint32_t)(nr * 128 + k8 * 32 + ((lg & 1) << 4)));
    }

    float acc[2][6][4] = {};

    auto prefetch = [&](int kt) {        // buffer kt (0..2)
        uint32_t ab  = s0 + GOFF_A + kt * 8192;
        uint32_t bbf = s0 + GOFF_B + kt * 24576;
        {
            int r = tid >> 2, f = tid & 3;
            CP_ASYNC16(ab + sw128((uint32_t)(r * 128 + f * 32)),
                       g_ow + (size_t)(m0 + r) * Cn + kt * 64 + f * 16);
            CP_ASYNC16(ab + sw128((uint32_t)(r * 128 + f * 32 + 16)),
                       g_ow + (size_t)(m0 + r) * Cn + kt * 64 + f * 16 + 8);
        }
        const __half* wsrc = Wt + kt * 64;
#pragma unroll
        for (int i = 0; i < 6; ++i) {
            int ss = tid + i * 256;
            int bn = ss >> 3, bf = ss & 7;
            CP_ASYNC16(bbf + sw128((uint32_t)(bn * 128 + bf * 16)),
                       wsrc + (size_t)bn * Cn + bf * 8);
        }
    };

    prefetch(0); CP_COMMIT();
    prefetch(1); CP_COMMIT();
    prefetch(2); CP_COMMIT();

    for (int kt = 0; kt < 3; ++kt) {
        if (kt == 0)      CP_WAIT2();
        else if (kt == 1) CP_WAIT1();
        else              CP_WAIT0();
        __syncthreads();
        const uint32_t abase = s0 + GOFF_A + kt * 8192;
        const uint32_t bbase = s0 + GOFF_B + kt * 24576;
#pragma unroll
        for (int k8 = 0; k8 < 4; ++k8) {
            uint32_t af[2][4];
#pragma unroll
            for (int mt = 0; mt < 2; ++mt)
                LDSM4(af[mt][0], af[mt][1], af[mt][2], af[mt][3], abase + offA[mt][k8]);
            uint32_t bfr[6][2];
#pragma unroll
            for (int np = 0; np < 3; ++np)
                LDSM4(bfr[2 * np][0], bfr[2 * np][1], bfr[2 * np + 1][0], bfr[2 * np + 1][1],
                      bbase + offB[np][k8]);
#pragma unroll
            for (int mt = 0; mt < 2; ++mt)
#pragma unroll
                for (int nt = 0; nt < 6; ++nt)
                    MMA_F16(acc[mt][nt], af[mt], bfr[nt]);
        }
    }

    const int col0 = wn * 48 + (lane & 3) * 2;
    float* ob = out + (size_t)bb * CHW;
#pragma unroll
    for (int mt = 0; mt < 2; ++mt)
#pragma unroll
        for (int hf = 0; hf < 2; ++hf) {
            int rem = rem0 + wm * 32 + mt * 16 + hf * 8 + (lane >> 2);
#pragma unroll
            for (int nt = 0; nt < 6; ++nt) {
#pragma unroll
                for (int j = 0; j < 2; ++j) {
                    int c = col0 + nt * 8 + j;
                    ob[(size_t)c * HW + rem] = acc[mt][nt][hf * 2 + j] + sbias[c];
                }
            }
        }
}

// =====================================================================
// K2: per-window attention, fp16 (FROZEN from round 14).
// =====================================================================
constexpr int A_QB0 = 0;
constexpr int A_P   = 12544;
constexpr int A_VT  = 0;
constexpr int A_S   = 25088;
constexpr int SMEM_ATTN_BYTES = 25088 + 17408 + 128;   // 42624

__global__ __launch_bounds__(128, 5) void k_attn_mma()
{
    extern __shared__ char smraw[];
    uint32_t sraw = (uint32_t)__cvta_generic_to_shared(smraw);
    const uint32_t s0 = (sraw + 127) & ~127u;
    char* sm = smraw + (s0 - sraw);

    const int tid  = threadIdx.x;
    const int lane = tid & 31, wm = tid >> 5;
    const int lg   = lane >> 3, lr = lane & 7;
    const int win  = blockIdx.x;

    const __half* qg = g_q + (size_t)win * P * Cn;
    const __half* kg = g_k + (size_t)win * P * Cn;
    const __half* vg = g_v + (size_t)win * P * Cn;
    float* sS = (float*)(sm + A_S);

    const int rowA      = wm * 16 + ((lg & 1) << 3) + lr;
    const uint32_t selA = (lg >> 1) << 4;
    const int nrb       = ((lg >> 1) << 3) + lr;
    const uint32_t selB = (lg & 1) << 4;

    auto prefQK = [&](int kt, int buf) {
        uint32_t qb = s0 + A_QB0 + buf * 12544;
        uint32_t kb = qb + 6272;
        for (int s = tid; s < 392; s += 128) {
            int row = s >> 3, f = s & 7;
            uint32_t o = sw128((uint32_t)(row * 128 + f * 16));
            CP_ASYNC16(qb + o, qg + (size_t)row * Cn + kt * 64 + f * 8);
            CP_ASYNC16(kb + o, kg + (size_t)row * Cn + kt * 64 + f * 8);
        }
    };

    float acc[8][4] = {};
    prefQK(0, 0); CP_COMMIT();
    for (int kt = 0; kt < 3; ++kt) {
        const int cur = kt & 1;
        if (kt < 2) { prefQK(kt + 1, cur ^ 1); CP_COMMIT(); CP_WAIT1(); }
        else        { CP_WAIT0(); }
        __syncthreads();
        const uint32_t qb = s0 + A_QB0 + cur * 12544;
        const uint32_t kb = qb + 6272;
#pragma unroll
        for (int x = 0; x < 4; ++x) {
            uint32_t af[4];
            LDSM4(af[0], af[1], af[2], af[3],
                  qb + sw128((uint32_t)(rowA * 128 + x * 32) + selA));
            uint32_t bfr[8][2];
#pragma unroll
            for (int np = 0; np < 4; ++np) {
                int nr = np * 16 + nrb;
                LDSM4(bfr[2 * np][0], bfr[2 * np][1], bfr[2 * np + 1][0], bfr[2 * np + 1][1],
                      kb + sw128((uint32_t)(nr * 128 + x * 32) + selB));
            }
#pragma unroll
            for (int nt = 0; nt < 8; ++nt)
                MMA_F16(acc[nt], af, bfr[nt]);
        }
        __syncthreads();
    }

    const float sc = 0.07216878364870323f;     // 1/sqrt(192)
    {
        int rb = wm * 16 + (lane >> 2);
        int cb = (lane & 3) * 2;
#pragma unroll
        for (int hf = 0; hf < 2; ++hf) {
            int i = rb + hf * 8;
#pragma unroll
            for (int nt = 0; nt < 8; ++nt) {
                float2 v;
                v.x = acc[nt][hf * 2 + 0] * sc;
                v.y = acc[nt][hf * 2 + 1] * sc;
                *(float2*)(sS + i * 68 + nt * 8 + cb) = v;
            }
        }
    }
    __syncthreads();

    // softmax (2 threads/row, full-warp shfl); probs -> fp16 P buffer
    {
        const int row = tid >> 1, half = tid & 1;
        const bool valid = (row < P);
        float* r = sS + row * 68;
        char* pP = sm + A_P;
        float mx = -1e30f;
        if (valid)
            for (int j = half; j < P; j += 2) mx = fmaxf(mx, r[j]);
        mx = fmaxf(mx, __shfl_xor_sync(0xFFFFFFFFu, mx, 1));
        float sum = 0.f;
        float ev[25];
        int cnt = 0;
        if (valid)
            for (int j = half; j < P; j += 2) { float e = __expf(r[j] - mx); ev[cnt++] = e; sum += e; }
        sum += __shfl_xor_sync(0xFFFFFFFFu, sum, 1);
        if (valid) {
            float inv = 1.f / sum;
            cnt = 0;
            for (int j = half; j < P; j += 2)
                *(__half*)(pP + sw128((uint32_t)(row * 128 + j * 2))) =
                    __float2half_rn(ev[cnt++] * inv);
            for (int j = P + half; j < 64; j += 2)
                *(__half*)(pP + sw128((uint32_t)(row * 128 + j * 2))) = __float2half_rn(0.f);
        }
    }
    // zero vT pad k-columns (j=50..63) once
    {
        const __half2 z = __floats2half2_rn(0.f, 0.f);
        for (int s = tid; s < 448; s += 128) {
            int c = s / 7, jj = 50 + (s - (s / 7) * 7) * 2;
            *(__half2*)(sm + A_VT + sw128((uint32_t)(c * 128 + jj * 2))) = z;
        }
    }
    __syncthreads();

    // Phase B: O = P @ V, 3 chunks of 64 channels
    const int bbw = win >> 10, wh = (win >> 5) & 31, ww = win & 31;
    for (int cc = 0; cc < 3; ++cc) {
        if (cc > 0) __syncthreads();
        const int c0 = cc * 64;
        for (int s = tid; s < 200; s += 128) {
            int jp = s >> 3, cg = s & 7;
            int j0 = jp * 2;
            uint4 va = *(const uint4*)(vg + (size_t)j0 * Cn + c0 + cg * 8);
            uint4 vb = make_uint4(0u, 0u, 0u, 0u);
            if (j0 + 1 < P)
                vb = *(const uint4*)(vg + (size_t)(j0 + 1) * Cn + c0 + cg * 8);
            uint32_t ca[4] = {va.x, va.y, va.z, va.w};
            uint32_t cbu[4] = {vb.x, vb.y, vb.z, vb.w};
#pragma unroll
            for (int q = 0; q < 4; ++q) {
                __half2 ha = *(__half2*)&ca[q];
                __half2 hb = *(__half2*)&cbu[q];
                int c = cg * 8 + q * 2;
                *(__half2*)(sm + A_VT + sw128((uint32_t)(c * 128 + jp * 4)))       = __lows2half2(ha, hb);
                *(__half2*)(sm + A_VT + sw128((uint32_t)((c + 1) * 128 + jp * 4))) = __highs2half2(ha, hb);
            }
        }
        __syncthreads();

        float acc2[8][4] = {};
#pragma unroll
        for (int x = 0; x < 4; ++x) {
            uint32_t af[4];
            LDSM4(af[0], af[1], af[2], af[3],
                  s0 + A_P + sw128((uint32_t)(rowA * 128 + x * 32) + selA));
            uint32_t bfr[8][2];
#pragma unroll
            for (int np = 0; np < 4; ++np) {
                int nr = np * 16 + nrb;
                LDSM4(bfr[2 * np][0], bfr[2 * np][1], bfr[2 * np + 1][0], bfr[2 * np + 1][1],
                      s0 + A_VT + sw128((uint32_t)(nr * 128 + x * 32) + selB));
            }
#pragma unroll
            for (int nt = 0; nt < 8; ++nt)
                MMA_F16(acc2[nt], af, bfr[nt]);
        }

        int rb = wm * 16 + (lane >> 2);
        int cb = (lane & 3) * 2;
#pragma unroll
        for (int hf = 0; hf < 2; ++hf) {
            int i = rb + hf * 8;
            if (i < P) {
                int ph = i / WSz, pw = i - ph * WSz;
                int m = bbw * HW + (wh * WSz + ph) * Wn + ww * WSz + pw;
                __half* op = g_ow + (size_t)m * Cn + c0 + cb;
#pragma unroll
                for (int nt = 0; nt < 8; ++nt)
                    *(__half2*)(op + nt * 8) = __floats2half2_rn(
                        acc2[nt][hf * 2 + 0], acc2[nt][hf * 2 + 1]);
            }
        }
    }
}

// =====================================================================
extern "C" void kernel_launch(void* const* d_in, const int* in_sizes, int n_in,
                              void* d_out, int out_size)
{
    const float* x  = (const float*)d_in[0];
    const float* Wq = (const float*)d_in[1];
    const float* bq = (const float*)d_in[2];
    const float* Wk = (const float*)d_in[3];
    const float* bk = (const float*)d_in[4];
    const float* Wv = (const float*)d_in[5];
    const float* bv = (const float*)d_in[6];
    const float* Wo = (const float*)d_in[7];
    const float* bo = (const float*)d_in[8];
    float* out = (float*)d_out;

    cudaFuncSetAttribute(k_qkv3,      cudaFuncAttributeMaxDynamicSharedMemorySize, SMEM_QKV_BYTES);
    cudaFuncSetAttribute(k_oproj_mma, cudaFuncAttributeMaxDynamicSharedMemorySize, SMEM_GEMM_BYTES);
    cudaFuncSetAttribute(k_attn_mma,  cudaFuncAttributeMaxDynamicSharedMemorySize, SMEM_ATTN_BYTES);

    k_prep_w<<<(4 * Cn * Cn) / 256, 256>>>(Wq, Wk, Wv, Wo);

    k_qkv3<<<MT / 64, 256, SMEM_QKV_BYTES>>>(x, bq, bk, bv);

    k_attn_mma<<<NWIN, 128, SMEM_ATTN_BYTES>>>();

    k_oproj_mma<<<MT / 64, 256, SMEM_GEMM_BYTES>>>(bo, out);
}

// round 16
// speedup vs baseline: 1.2633x; 1.0253x over previous
#include <cuda_runtime.h>
#include <cuda_fp16.h>
#include <cstdint>

// ---------------- problem constants ----------------
constexpr int Bn  = 8;
constexpr int Cn  = 192;
constexpr int Hn  = 224;
constexpr int Wn  = 224;
constexpr int WSz = 7;
constexpr int HW  = Hn * Wn;          // 50176
constexpr int CHW = Cn * HW;
constexpr int NH  = Hn / WSz;         // 32
constexpr int NWb = NH * NH;          // 1024
constexpr int NWIN = Bn * NWb;        // 8192
constexpr int P   = WSz * WSz;        // 49
constexpr int MT  = Bn * HW;          // 401408

// ---------------- scratch ----------------
__device__ __align__(16) __half g_q [(size_t)NWIN * P * Cn];
__device__ __align__(16) __half g_k [(size_t)NWIN * P * Cn];
__device__ __align__(16) __half g_v [(size_t)NWIN * P * Cn];
__device__ __align__(16) __half g_ow[(size_t)MT * Cn];
__device__ __align__(16) __half g_whf[4][Cn * Cn];    // fp16 weights

// ---------------- helpers ----------------
__device__ __forceinline__ uint32_t sw128(uint32_t o) { return o ^ ((o >> 3) & 0x70); }

#define LDSM4(d0, d1, d2, d3, a) \
    asm volatile("ldmatrix.sync.aligned.m8n8.x4.shared.b16 {%0,%1,%2,%3},[%4];" \
        : "=r"(d0), "=r"(d1), "=r"(d2), "=r"(d3) : "r"(a))

#define MMA_F16(c, a, b) \
    asm volatile("mma.sync.aligned.m16n8k16.row.col.f32.f16.f16.f32 " \
        "{%0,%1,%2,%3},{%4,%5,%6,%7},{%8,%9},{%0,%1,%2,%3};" \
        : "+f"((c)[0]), "+f"((c)[1]), "+f"((c)[2]), "+f"((c)[3]) \
        : "r"((a)[0]), "r"((a)[1]), "r"((a)[2]), "r"((a)[3]), \
          "r"((b)[0]), "r"((b)[1]))

// L2-only cp.async (R14 win)
#define CP_ASYNC16(dst, src) \
    asm volatile("cp.async.cg.shared.global [%0],[%1],16;" :: "r"(dst), "l"(src))
#define CP_COMMIT()  asm volatile("cp.async.commit_group;" ::: "memory")
#define CP_WAIT2()   asm volatile("cp.async.wait_group 2;" ::: "memory")
#define CP_WAIT1()   asm volatile("cp.async.wait_group 1;" ::: "memory")
#define CP_WAIT0()   asm volatile("cp.async.wait_group 0;" ::: "memory")

// =====================================================================
// prepass: weights -> fp16 once (tiny)
// =====================================================================
__global__ void k_prep_w(const float* __restrict__ Wq, const float* __restrict__ Wk,
                         const float* __restrict__ Wv, const float* __restrict__ Wo)
{
    int idx = blockIdx.x * 256 + threadIdx.x;
    int wsel = idx / (Cn * Cn);
    int r    = idx - wsel * (Cn * Cn);
    const float* W = (wsel == 0) ? Wq : (wsel == 1) ? Wk : (wsel == 2) ? Wv : Wo;
    g_whf[wsel][r] = __float2half_rn(W[r]);
}

// =====================================================================
// K1: single-pass fused QKV GEMM, all fp16 (FROZEN from round 15).
// =====================================================================
constexpr int Q3_A   = 0;          // 3 x 8192 = 24576
constexpr int Q3_B   = 24576;      // 3 x 24576 -> 98304
constexpr int Q3_BI  = 98304;      // 576 floats
constexpr int SMEM_QKV_BYTES = 98304 + 2304 + 128;   // 100736

__global__ __launch_bounds__(256, 2) void k_qkv3(
    const float* __restrict__ x,
    const float* __restrict__ bq, const float* __restrict__ bk,
    const float* __restrict__ bv)
{
    extern __shared__ char smraw[];
    uint32_t sraw = (uint32_t)__cvta_generic_to_shared(smraw);
    const uint32_t s0 = (sraw + 127) & ~127u;
    char* sm = smraw + (s0 - sraw);
    float* sbias = (float*)(sm + Q3_BI);

    const int tid  = threadIdx.x;
    const int lane = tid & 31, wid = tid >> 5;
    const int wm   = wid >> 2, wn = wid & 3;
    const int m0   = blockIdx.x * 64;
    const int bb   = m0 / HW, rem0 = m0 - bb * HW;
    const float* xb = x + (size_t)bb * CHW + rem0;

    if (tid < 192) {
        sbias[tid]       = bq[tid];
        sbias[192 + tid] = bk[tid];
        sbias[384 + tid] = bv[tid];
    }

    const int lg = lane >> 3, lr = lane & 7;

    uint32_t offA[2][4], offB[3][4];
#pragma unroll
    for (int mt = 0; mt < 2; ++mt) {
        int row = wm * 32 + mt * 16 + ((lg & 1) << 3) + lr;
#pragma unroll
        for (int k8 = 0; k8 < 4; ++k8)
            offA[mt][k8] = sw128((uint32_t)(row * 128 + k8 * 32 + ((lg >> 1) << 4)));
    }
#pragma unroll
    for (int np = 0; np < 3; ++np) {
        int nr = wn * 48 + np * 16 + ((lg >> 1) << 3) + lr;
#pragma unroll
        for (int k8 = 0; k8 < 4; ++k8)
            offB[np][k8] = sw128((uint32_t)(nr * 128 + k8 * 32 + ((lg & 1) << 4)));
    }

    int scat[2][2];
#pragma unroll
    for (int mt = 0; mt < 2; ++mt)
#pragma unroll
        for (int hf = 0; hf < 2; ++hf) {
            int rem = rem0 + wm * 32 + mt * 16 + hf * 8 + (lane >> 2);
            int h = rem / Wn, w = rem - h * Wn;
            int hb = h / WSz, wb = w / WSz;
            int win = bb * NWb + hb * NH + wb;
            int pp  = (h - hb * WSz) * WSz + (w - wb * WSz);
            scat[mt][hf] = win * P + pp;
        }

    const int arow = tid & 63;
    const int aseg = tid >> 6;           // 0..3, 16 k each
    float areg[16];

    auto ldA = [&](int c) {
        const float* s = xb + (size_t)(c * 64 + aseg * 16) * HW + arow;
#pragma unroll
        for (int j = 0; j < 16; ++j) areg[j] = s[(size_t)j * HW];
    };
    auto stA = [&](int c) {
        char* ab = sm + Q3_A + c * 8192;
        uint32_t h[8];
#pragma unroll
        for (int q = 0; q < 8; ++q) {
            __half2 p = __floats2half2_rn(areg[2 * q], areg[2 * q + 1]);
            h[q] = *(uint32_t*)&p;
        }
        uint4 u0 = make_uint4(h[0], h[1], h[2], h[3]);
        uint4 u1 = make_uint4(h[4], h[5], h[6], h[7]);
        *(uint4*)(ab + sw128((uint32_t)(arow * 128 + aseg * 32)))      = u0;
        *(uint4*)(ab + sw128((uint32_t)(arow * 128 + aseg * 32 + 16))) = u1;
    };

    auto prefB = [&](int t) {            // t = wsel*3 + kt ; buffer t%3
        const __half* wsrc = g_whf[t / 3] + (t % 3) * 64;
        uint32_t bbf = s0 + Q3_B + (t % 3) * 24576;
#pragma unroll
        for (int i = 0; i < 6; ++i) {
            int ss = tid + i * 256;
            int bn = ss >> 3, bf = ss & 7;
            CP_ASYNC16(bbf + sw128((uint32_t)(bn * 128 + bf * 16)),
                       wsrc + (size_t)bn * Cn + bf * 8);
        }
    };

    float acc[2][6][4] = {};

    auto gemm_step = [&](uint32_t abase, uint32_t bbase) {
#pragma unroll
        for (int k8 = 0; k8 < 4; ++k8) {
            uint32_t af[2][4];
#pragma unroll
            for (int mt = 0; mt < 2; ++mt)
                LDSM4(af[mt][0], af[mt][1], af[mt][2], af[mt][3], abase + offA[mt][k8]);
            uint32_t bfr[6][2];
#pragma unroll
            for (int np = 0; np < 3; ++np)
                LDSM4(bfr[2 * np][0], bfr[2 * np][1], bfr[2 * np + 1][0], bfr[2 * np + 1][1],
                      bbase + offB[np][k8]);
#pragma unroll
            for (int mt = 0; mt < 2; ++mt)
#pragma unroll
                for (int nt = 0; nt < 6; ++nt)
                    MMA_F16(acc[mt][nt], af[mt], bfr[nt]);
        }
    };

    __half* dsts[3] = {g_q, g_k, g_v};
    auto do_epi = [&](int w) {
        __half* dst = dsts[w];
        const float* bofs = sbias + w * 192;
        const int col0 = wn * 48 + (lane & 3) * 2;
#pragma unroll
        for (int mt = 0; mt < 2; ++mt)
#pragma unroll
            for (int hf = 0; hf < 2; ++hf) {
                __half* dp = dst + (size_t)scat[mt][hf] * Cn;
#pragma unroll
                for (int nt = 0; nt < 6; ++nt) {
                    int c = col0 + nt * 8;
                    *(__half2*)(dp + c) = __floats2half2_rn(
                        acc[mt][nt][hf * 2 + 0] + bofs[c],
                        acc[mt][nt][hf * 2 + 1] + bofs[c + 1]);
                    acc[mt][nt][hf * 2 + 0] = 0.f;
                    acc[mt][nt][hf * 2 + 1] = 0.f;
                }
            }
    };

    ldA(0);
    prefB(0); CP_COMMIT();
    prefB(1); CP_COMMIT();
    stA(0);
    ldA(1);

#pragma unroll 3
    for (int t = 0; t < 9; ++t) {
        if (t < 8) CP_WAIT1();
        else       CP_WAIT0();
        __syncthreads();
        if (t < 7) { prefB(t + 2); CP_COMMIT(); }
        if (t == 0) { stA(1); ldA(2); }
        if (t == 1) { stA(2); }
        gemm_step(s0 + Q3_A + (t - (t / 3) * 3) * 8192,
                  s0 + Q3_B + (t % 3) * 24576);
        if ((t - (t / 3) * 3) == 2) do_epi(t / 3);
    }
}

// =====================================================================
// K3: output projection GEMM, all fp16 (FROZEN from round 15).
// =====================================================================
constexpr int GOFF_A  = 0;          // 3 x 8192 = 24576
constexpr int GOFF_B  = 24576;      // 3 x 24576 -> 98304
constexpr int GOFF_BI = 98304;
constexpr int SMEM_GEMM_BYTES = 98304 + 768 + 128;

__global__ __launch_bounds__(256, 2) void k_oproj_mma(
    const float* __restrict__ bo, float* __restrict__ out)
{
    extern __shared__ char smraw[];
    uint32_t sraw = (uint32_t)__cvta_generic_to_shared(smraw);
    const uint32_t s0 = (sraw + 127) & ~127u;
    char* sm = smraw + (s0 - sraw);
    float* sbias = (float*)(sm + GOFF_BI);

    const int tid  = threadIdx.x;
    const int lane = tid & 31, wid = tid >> 5;
    const int wm   = wid >> 2, wn = wid & 3;
    const int m0   = blockIdx.x * 64;
    const int bb   = m0 / HW, rem0 = m0 - bb * HW;
    const __half* Wt = g_whf[3];

    if (tid < 192) sbias[tid] = bo[tid];

    const int lg = lane >> 3, lr = lane & 7;

    uint32_t offA[2][4], offB[3][4];
#pragma unroll
    for (int mt = 0; mt < 2; ++mt) {
        int row = wm * 32 + mt * 16 + ((lg & 1) << 3) + lr;
#pragma unroll
        for (int k8 = 0; k8 < 4; ++k8)
            offA[mt][k8] = sw128((uint32_t)(row * 128 + k8 * 32 + ((lg >> 1) << 4)));
    }
#pragma unroll
    for (int np = 0; np < 3; ++np) {
        int nr = wn * 48 + np * 16 + ((lg >> 1) << 3) + lr;
#pragma unroll
        for (int k8 = 0; k8 < 4; ++k8)
            offB[np][k8] = sw128((uint32_t)(nr * 128 + k8 * 32 + ((lg & 1) << 4)));
    }

    float acc[2][6][4] = {};

    auto prefetch = [&](int kt) {        // buffer kt (0..2)
        uint32_t ab  = s0 + GOFF_A + kt * 8192;
        uint32_t bbf = s0 + GOFF_B + kt * 24576;
        {
            int r = tid >> 2, f = tid & 3;
            CP_ASYNC16(ab + sw128((uint32_t)(r * 128 + f * 32)),
                       g_ow + (size_t)(m0 + r) * Cn + kt * 64 + f * 16);
            CP_ASYNC16(ab + sw128((uint32_t)(r * 128 + f * 32 + 16)),
                       g_ow + (size_t)(m0 + r) * Cn + kt * 64 + f * 16 + 8);
        }
        const __half* wsrc = Wt + kt * 64;
#pragma unroll
        for (int i = 0; i < 6; ++i) {
            int ss = tid + i * 256;
            int bn = ss >> 3, bf = ss & 7;
            CP_ASYNC16(bbf + sw128((uint32_t)(bn * 128 + bf * 16)),
                       wsrc + (size_t)bn * Cn + bf * 8);
        }
    };

    prefetch(0); CP_COMMIT();
    prefetch(1); CP_COMMIT();
    prefetch(2); CP_COMMIT();

    for (int kt = 0; kt < 3; ++kt) {
        if (kt == 0)      CP_WAIT2();
        else if (kt == 1) CP_WAIT1();
        else              CP_WAIT0();
        __syncthreads();
        const uint32_t abase = s0 + GOFF_A + kt * 8192;
        const uint32_t bbase = s0 + GOFF_B + kt * 24576;
#pragma unroll
        for (int k8 = 0; k8 < 4; ++k8) {
            uint32_t af[2][4];
#pragma unroll
            for (int mt = 0; mt < 2; ++mt)
                LDSM4(af[mt][0], af[mt][1], af[mt][2], af[mt][3], abase + offA[mt][k8]);
            uint32_t bfr[6][2];
#pragma unroll
            for (int np = 0; np < 3; ++np)
                LDSM4(bfr[2 * np][0], bfr[2 * np][1], bfr[2 * np + 1][0], bfr[2 * np + 1][1],
                      bbase + offB[np][k8]);
#pragma unroll
            for (int mt = 0; mt < 2; ++mt)
#pragma unroll
                for (int nt = 0; nt < 6; ++nt)
                    MMA_F16(acc[mt][nt], af[mt], bfr[nt]);
        }
    }

    const int col0 = wn * 48 + (lane & 3) * 2;
    float* ob = out + (size_t)bb * CHW;
#pragma unroll
    for (int mt = 0; mt < 2; ++mt)
#pragma unroll
        for (int hf = 0; hf < 2; ++hf) {
            int rem = rem0 + wm * 32 + mt * 16 + hf * 8 + (lane >> 2);
#pragma unroll
            for (int nt = 0; nt < 6; ++nt) {
#pragma unroll
                for (int j = 0; j < 2; ++j) {
                    int c = col0 + nt * 8 + j;
                    ob[(size_t)c * HW + rem] = acc[mt][nt][hf * 2 + j] + sbias[c];
                }
            }
        }
}

// =====================================================================
// K2: per-window attention, fp16. Phase B: ping-pong vT buffers +
//     register-staged v prefetch, ONE sync per chunk.
//   vT buf0 at 0 (dead q/k buf0), vT buf1 at 25088 (dead S region).
// =====================================================================
constexpr int A_QB0 = 0;
constexpr int A_P   = 12544;
constexpr int A_VT0 = 0;
constexpr int A_S   = 25088;
constexpr int A_VT1 = 25088;
constexpr int SMEM_ATTN_BYTES = 25088 + 17408 + 128;   // 42624

__global__ __launch_bounds__(128, 5) void k_attn_mma()
{
    extern __shared__ char smraw[];
    uint32_t sraw = (uint32_t)__cvta_generic_to_shared(smraw);
    const uint32_t s0 = (sraw + 127) & ~127u;
    char* sm = smraw + (s0 - sraw);

    const int tid  = threadIdx.x;
    const int lane = tid & 31, wm = tid >> 5;
    const int lg   = lane >> 3, lr = lane & 7;
    const int win  = blockIdx.x;

    const __half* qg = g_q + (size_t)win * P * Cn;
    const __half* kg = g_k + (size_t)win * P * Cn;
    const __half* vg = g_v + (size_t)win * P * Cn;
    float* sS = (float*)(sm + A_S);

    const int rowA      = wm * 16 + ((lg & 1) << 3) + lr;
    const uint32_t selA = (lg >> 1) << 4;
    const int nrb       = ((lg >> 1) << 3) + lr;
    const uint32_t selB = (lg & 1) << 4;

    // ---------------- Phase A: S = q k^T ----------------
    auto prefQK = [&](int kt, int buf) {
        uint32_t qb = s0 + A_QB0 + buf * 12544;
        uint32_t kb = qb + 6272;
        for (int s = tid; s < 392; s += 128) {
            int row = s >> 3, f = s & 7;
            uint32_t o = sw128((uint32_t)(row * 128 + f * 16));
            CP_ASYNC16(qb + o, qg + (size_t)row * Cn + kt * 64 + f * 8);
            CP_ASYNC16(kb + o, kg + (size_t)row * Cn + kt * 64 + f * 8);
        }
    };

    float acc[8][4] = {};
    prefQK(0, 0); CP_COMMIT();
    for (int kt = 0; kt < 3; ++kt) {
        const int cur = kt & 1;
        if (kt < 2) { prefQK(kt + 1, cur ^ 1); CP_COMMIT(); CP_WAIT1(); }
        else        { CP_WAIT0(); }
        __syncthreads();
        const uint32_t qb = s0 + A_QB0 + cur * 12544;
        const uint32_t kb = qb + 6272;
#pragma unroll
        for (int x = 0; x < 4; ++x) {
            uint32_t af[4];
            LDSM4(af[0], af[1], af[2], af[3],
                  qb + sw128((uint32_t)(rowA * 128 + x * 32) + selA));
            uint32_t bfr[8][2];
#pragma unroll
            for (int np = 0; np < 4; ++np) {
                int nr = np * 16 + nrb;
                LDSM4(bfr[2 * np][0], bfr[2 * np][1], bfr[2 * np + 1][0], bfr[2 * np + 1][1],
                      kb + sw128((uint32_t)(nr * 128 + x * 32) + selB));
            }
#pragma unroll
            for (int nt = 0; nt < 8; ++nt)
                MMA_F16(acc[nt], af, bfr[nt]);
        }
        __syncthreads();
    }

    const float sc = 0.07216878364870323f;     // 1/sqrt(192)
    {
        int rb = wm * 16 + (lane >> 2);
        int cb = (lane & 3) * 2;
#pragma unroll
        for (int hf = 0; hf < 2; ++hf) {
            int i = rb + hf * 8;
#pragma unroll
            for (int nt = 0; nt < 8; ++nt) {
                float2 v;
                v.x = acc[nt][hf * 2 + 0] * sc;
                v.y = acc[nt][hf * 2 + 1] * sc;
                *(float2*)(sS + i * 68 + nt * 8 + cb) = v;
            }
        }
    }
    __syncthreads();

    // softmax (2 threads/row, full-warp shfl); probs -> fp16 P buffer
    {
        const int row = tid >> 1, half = tid & 1;
        const bool valid = (row < P);
        float* r = sS + row * 68;
        char* pP = sm + A_P;
        float mx = -1e30f;
        if (valid)
            for (int j = half; j < P; j += 2) mx = fmaxf(mx, r[j]);
        mx = fmaxf(mx, __shfl_xor_sync(0xFFFFFFFFu, mx, 1));
        float sum = 0.f;
        float ev[25];
        int cnt = 0;
        if (valid)
            for (int j = half; j < P; j += 2) { float e = __expf(r[j] - mx); ev[cnt++] = e; sum += e; }
        sum += __shfl_xor_sync(0xFFFFFFFFu, sum, 1);
        if (valid) {
            float inv = 1.f / sum;
            cnt = 0;
            for (int j = half; j < P; j += 2)
                *(__half*)(pP + sw128((uint32_t)(row * 128 + j * 2))) =
                    __float2half_rn(ev[cnt++] * inv);
            for (int j = P + half; j < 64; j += 2)
                *(__half*)(pP + sw128((uint32_t)(row * 128 + j * 2))) = __float2half_rn(0.f);
        }
    }
    // NOTE: softmax reads sS (S region) above; the pad/stV writes to
    // A_VT1 (same region) happen only after the __syncthreads below.

    // ---------------- Phase B: O = P @ V, pipelined ----------------
    const int bbw = win >> 10, wh = (win >> 5) & 31, ww = win & 31;

    // register-staged v loader: slot = jq(13) x cg(8); 4 rows x 8 chans
    const int slot = tid;
    const int jq = slot >> 3, cg = slot & 7;     // jq 0..15 (active <13)
    const bool vact = (slot < 104);
    uint32_t vw[16];

    auto ldV = [&](int cc) {
        if (vact) {
            const __half* src = vg + cc * 64 + cg * 8;
#pragma unroll
            for (int r = 0; r < 4; ++r) {
                int j = jq * 4 + r;
                uint4 u = make_uint4(0u, 0u, 0u, 0u);
                if (j < P) u = *(const uint4*)(src + (size_t)j * Cn);
                vw[r * 4 + 0] = u.x; vw[r * 4 + 1] = u.y;
                vw[r * 4 + 2] = u.z; vw[r * 4 + 3] = u.w;
            }
        }
    };
    auto stV = [&](uint32_t vb) {
        if (vact) {
#pragma unroll
            for (int q = 0; q < 4; ++q) {
                __half2 h0 = *(__half2*)&vw[0 * 4 + q];
                __half2 h1 = *(__half2*)&vw[1 * 4 + q];
                __half2 h2 = *(__half2*)&vw[2 * 4 + q];
                __half2 h3 = *(__half2*)&vw[3 * 4 + q];
                int c = cg * 8 + q * 2;
                uint32_t o0 = vb + sw128((uint32_t)(c * 128 + jq * 8));
                uint32_t o1 = vb + sw128((uint32_t)((c + 1) * 128 + jq * 8));
                *(__half2*)(sm + (o0 - s0))     = __lows2half2(h0, h1);
                *(__half2*)(sm + (o0 - s0) + 4) = __lows2half2(h2, h3);
                *(__half2*)(sm + (o1 - s0))     = __highs2half2(h0, h1);
                *(__half2*)(sm + (o1 - s0) + 4) = __highs2half2(h2, h3);
            }
        }
    };

    // chunk 0 into regs; pad both buffers' k-columns j=50..63
    ldV(0);
    {
        const __half2 z = __floats2half2_rn(0.f, 0.f);
        for (int s = tid; s < 448; s += 128) {
            int c = s / 7, jj = 50 + (s - (s / 7) * 7) * 2;
            uint32_t o = sw128((uint32_t)(c * 128 + jj * 2));
            *(__half2*)(sm + A_VT0 + o) = z;
            *(__half2*)(sm + A_VT1 + o) = z;
        }
    }
    stV(s0 + A_VT0);
    ldV(1);
    __syncthreads();    // vT0 + P + pads visible; S-region reads done

    for (int cc = 0; cc < 3; ++cc) {
        const uint32_t vb = (cc & 1) ? (s0 + A_VT1) : (s0 + A_VT0);

        float acc2[8][4] = {};
#pragma unroll
        for (int x = 0; x < 4; ++x) {
            uint32_t af[4];
            LDSM4(af[0], af[1], af[2], af[3],
                  s0 + A_P + sw128((uint32_t)(rowA * 128 + x * 32) + selA));
            uint32_t bfr[8][2];
#pragma unroll
            for (int np = 0; np < 4; ++np) {
                int nr = np * 16 + nrb;
                LDSM4(bfr[2 * np][0], bfr[2 * np][1], bfr[2 * np + 1][0], bfr[2 * np + 1][1],
                      vb + sw128((uint32_t)(nr * 128 + x * 32) + selB));
            }
#pragma unroll
            for (int nt = 0; nt < 8; ++nt)
                MMA_F16(acc2[nt], af, bfr[nt]);
        }

        // epilogue: store chunk cc to g_ow
        {
            const int c0 = cc * 64;
            int rb = wm * 16 + (lane >> 2);
            int cb = (lane & 3) * 2;
#pragma unroll
            for (int hf = 0; hf < 2; ++hf) {
                int i = rb + hf * 8;
                if (i < P) {
                    int ph = i / WSz, pw = i - ph * WSz;
                    int m = bbw * HW + (wh * WSz + ph) * Wn + ww * WSz + pw;
                    __half* op = g_ow + (size_t)m * Cn + c0 + cb;
#pragma unroll
                    for (int nt = 0; nt < 8; ++nt)
                        *(__half2*)(op + nt * 8) = __floats2half2_rn(
                            acc2[nt][hf * 2 + 0], acc2[nt][hf * 2 + 1]);
                }
            }
        }

        if (cc < 2) {
            stV((cc & 1) ? (s0 + A_VT0) : (s0 + A_VT1));   // chunk cc+1
            if (cc == 0) ldV(2);
            __syncthreads();
        }
    }
}

// =====================================================================
extern "C" void kernel_launch(void* const* d_in, const int* in_sizes, int n_in,
                              void* d_out, int out_size)
{
    const float* x  = (const float*)d_in[0];
    const float* Wq = (const float*)d_in[1];
    const float* bq = (const float*)d_in[2];
    const float* Wk = (const float*)d_in[3];
    const float* bk = (const float*)d_in[4];
    const float* Wv = (const float*)d_in[5];
    const float* bv = (const float*)d_in[6];
    const float* Wo = (const float*)d_in[7];
    const float* bo = (const float*)d_in[8];
    float* out = (float*)d_out;

    cudaFuncSetAttribute(k_qkv3,      cudaFuncAttributeMaxDynamicSharedMemorySize, SMEM_QKV_BYTES);
    cudaFuncSetAttribute(k_oproj_mma, cudaFuncAttributeMaxDynamicSharedMemorySize, SMEM_GEMM_BYTES);
    cudaFuncSetAttribute(k_attn_mma,  cudaFuncAttributeMaxDynamicSharedMemorySize, SMEM_ATTN_BYTES);

    k_prep_w<<<(4 * Cn * Cn) / 256, 256>>>(Wq, Wk, Wv, Wo);

    k_qkv3<<<MT / 64, 256, SMEM_QKV_BYTES>>>(x, bq, bk, bv);

    k_attn_mma<<<NWIN, 128, SMEM_ATTN_BYTES>>>();

    k_oproj_mma<<<MT / 64, 256, SMEM_GEMM_BYTES>>>(bo, out);
}